// round 9
// baseline (speedup 1.0000x reference)
#include <cuda_runtime.h>
#include <cuda_bf16.h>
#include <math.h>
#include <stdint.h>

#define H 64
#define VOCAB 5
#define S 384
#define BATCH 8
#define NROWS (BATCH * S * S)       // 1,179,648
#define TILE_ROWS 64                // rows per CTA iteration (16 per warp)
#define NTILES (NROWS / TILE_ROWS)  // 18432
#define TPB 128
#define GRID_MAIN 592               // 148 SMs * 4 resident CTAs

// ---- dynamic smem layout ----
#define SM_BF    0
#define SM_WO8   49152
#define SM_BIAS  (SM_WO8 + 2048)
#define SMEM_BYTES (SM_BIAS + 768)   // 51968

__device__ uint2 g_bf[3][2][4][8][32];
__device__ float g_bias2[64];
__device__ float g_bias3[64];
__device__ float g_wop[64 * 8];
__device__ float g_bop[8];

static __device__ __forceinline__ unsigned short bfu(__nv_bfloat16 h) {
    return __bfloat16_as_ushort(h);
}

__global__ void prep_weights(const float* __restrict__ W1, const float* __restrict__ W2,
                             const float* __restrict__ W3, const float* __restrict__ ln_g) {
    int idx = blockIdx.x * blockDim.x + threadIdx.x;
    if (idx >= 3 * 2 * 4 * 8 * 32) return;
    int lane = idx & 31;
    int nt = (idx >> 5) & 7;
    int ks = (idx >> 8) & 3;
    int t  = (idx >> 10) & 1;
    int l  = idx >> 11;
    const float* W = (l == 0) ? W1 : (l == 1) ? W2 : W3;
    int n  = nt * 8 + (lane >> 2);
    int k0 = ks * 16 + (lane & 3) * 2;

    unsigned short e[4];
    int kk[4] = {k0, k0 + 1, k0 + 8, k0 + 9};
    for (int i = 0; i < 4; i++) {
        float w = W[kk[i] * H + n];
        if (l > 0) w *= ln_g[kk[i]];
        __nv_bfloat16 hi = __float2bfloat16_rn(w);
        if (t == 0) e[i] = bfu(hi);
        else        e[i] = bfu(__float2bfloat16_rn(w - __bfloat162float(hi)));
    }
    uint2 r;
    r.x = (uint32_t)e[0] | ((uint32_t)e[1] << 16);
    r.y = (uint32_t)e[2] | ((uint32_t)e[3] << 16);
    g_bf[l][t][ks][nt][lane] = r;
}

__global__ void prep_fold(const float* __restrict__ W2, const float* __restrict__ b2,
                          const float* __restrict__ W3, const float* __restrict__ b3,
                          const float* __restrict__ ln_g, const float* __restrict__ ln_b,
                          const float* __restrict__ Wo, const float* __restrict__ bo) {
    int tid = threadIdx.x;   // 256 threads
    if (tid < 64) {
        float s2 = b2[tid], s3 = b3[tid];
        for (int k = 0; k < 64; k++) {
            const float lb = ln_b[k];
            s2 = fmaf(lb, W2[k * H + tid], s2);
            s3 = fmaf(lb, W3[k * H + tid], s3);
        }
        g_bias2[tid] = s2;
        g_bias3[tid] = s3;
    } else if (tid < 128) {
        int k = tid - 64;
        const float g = ln_g[k];
        for (int v = 0; v < 8; v++)
            g_wop[k * 8 + v] = (v < VOCAB) ? g * Wo[k * VOCAB + v] : 0.0f;
    } else if (tid < 136) {
        int v = tid - 128;
        float s = 0.0f;
        if (v < VOCAB) {
            s = bo[v];
            for (int k = 0; k < 64; k++) s = fmaf(ln_b[k], Wo[k * VOCAB + v], s);
        }
        g_bop[v] = s;
    }
}

static __device__ __forceinline__ void splitpk(float a, float b, uint32_t& hp, uint32_t& lp) {
    __nv_bfloat162 h2 = __floats2bfloat162_rn(a, b);
    uint32_t u = *(uint32_t*)&h2;
    float ha = __uint_as_float(u << 16);
    float hb = __uint_as_float(u & 0xFFFF0000u);
    __nv_bfloat162 l2 = __floats2bfloat162_rn(a - ha, b - hb);
    hp = u;
    lp = *(uint32_t*)&l2;
}

// Branch-free exact-gelu (A&S 7.1.26 erf, abs err <= 1.5e-7)
static __device__ __forceinline__ float gelu_f(float v) {
    const float z  = fabsf(v) * 0.70710678118654752f;
    const float t  = __fdividef(1.0f, fmaf(0.3275911f, z, 1.0f));
    float p = fmaf(1.061405429f, t, -1.453152027f);
    p = fmaf(p, t, 1.421413741f);
    p = fmaf(p, t, -0.284496736f);
    p = fmaf(p, t, 0.254829592f);
    p = p * t;
    const float e  = __expf(-z * z);
    const float er = fmaf(-p, e, 1.0f);
    const float es = copysignf(er, v);
    const float hv = 0.5f * v;
    return fmaf(hv, es, hv);
}

#define MMA(d, a, bx, by)                                                              \
    asm volatile("mma.sync.aligned.m16n8k16.row.col.f32.bf16.bf16.f32 "                \
        "{%0,%1,%2,%3}, {%4,%5,%6,%7}, {%8,%9}, {%0,%1,%2,%3};"                        \
        : "+f"(d[0]), "+f"(d[1]), "+f"(d[2]), "+f"(d[3])                               \
        : "r"(a[0]), "r"(a[1]), "r"(a[2]), "r"(a[3]), "r"(bx), "r"(by))

__global__ __launch_bounds__(TPB, 4)
void mma_mlp_kernel(const float* __restrict__ x,
                    const float* __restrict__ b1,
                    float* __restrict__ out) {
    extern __shared__ __align__(16) unsigned char smem[];
    uint2*  sBF   = (uint2*)(smem + SM_BF);
    float*  sWo8  = (float*)(smem + SM_WO8);
    float*  sBias = (float*)(smem + SM_BIAS);

    const int tid  = threadIdx.x;
    const int lane = tid & 31;
    const int warp = tid >> 5;
    const int q    = lane >> 2;
    const int tq   = lane & 3;

    {
        const uint4* src = (const uint4*)g_bf;
        uint4* dst = (uint4*)(smem + SM_BF);
        #pragma unroll
        for (int i = tid; i < 49152 / 16; i += TPB) dst[i] = src[i];
    }
    for (int i = tid; i < H * 8; i += TPB) sWo8[i] = g_wop[i];
    if (tid < H) {
        sBias[tid] = b1[tid];
        sBias[64 + tid] = g_bias2[tid];
        sBias[128 + tid] = g_bias3[tid];
    }
    __syncthreads();

    const float bo0 = g_bop[0], bo1 = g_bop[1], bo2 = g_bop[2],
                bo3 = g_bop[3], bo4 = g_bop[4];

    for (int tile = blockIdx.x; tile < NTILES; tile += gridDim.x) {
        const int rowbase = tile * TILE_ROWS + warp * 16;
        const float* xb = x + (size_t)rowbase * H;

        // 16 rows per warp: one m16 tile. A fragments hi/lo.
        uint32_t ahi[4][4], alo[4][4];
        #pragma unroll
        for (int kc = 0; kc < 4; kc++)
            #pragma unroll
            for (int h2 = 0; h2 < 2; h2++)
                #pragma unroll
                for (int rr = 0; rr < 2; rr++) {
                    const float2 v = *(const float2*)(xb + (size_t)(q + 8 * rr) * H
                                                      + kc * 16 + h2 * 8 + tq * 2);
                    splitpk(v.x, v.y, ahi[kc][h2 * 2 + rr], alo[kc][h2 * 2 + rr]);
                }

        float acc[8][4];
        float rs[2], cc[2];
        #pragma unroll
        for (int l = 0; l < 3; l++) {
            #pragma unroll
            for (int nt = 0; nt < 8; nt++) {
                const float2 bb = *(const float2*)(sBias + l * 64 + nt * 8 + tq * 2);
                acc[nt][0] = bb.x; acc[nt][1] = bb.y;
                acc[nt][2] = bb.x; acc[nt][3] = bb.y;
            }
            #pragma unroll
            for (int ks = 0; ks < 4; ks++) {
                #pragma unroll
                for (int nt = 0; nt < 8; nt++) {
                    const uint2 bh = sBF[(((l * 2 + 0) * 4 + ks) * 8 + nt) * 32 + lane];
                    const uint2 bl = sBF[(((l * 2 + 1) * 4 + ks) * 8 + nt) * 32 + lane];
                    MMA(acc[nt], ahi[ks], bh.x, bh.y);
                    MMA(acc[nt], alo[ks], bh.x, bh.y);
                    MMA(acc[nt], ahi[ks], bl.x, bl.y);
                }
            }

            // gelu + LN statistics
            float s0[2] = {0, 0}, s1[2] = {0, 0};
            #pragma unroll
            for (int nt = 0; nt < 8; nt++)
                #pragma unroll
                for (int i = 0; i < 4; i++) {
                    const float g = gelu_f(acc[nt][i]);
                    acc[nt][i] = g;
                    s0[i >> 1] += g;
                    s1[i >> 1] += g * g;
                }
            #pragma unroll
            for (int rr = 0; rr < 2; rr++) {
                float a = s0[rr], b = s1[rr];
                a += __shfl_xor_sync(0xFFFFFFFF, a, 1);
                b += __shfl_xor_sync(0xFFFFFFFF, b, 1);
                a += __shfl_xor_sync(0xFFFFFFFF, a, 2);
                b += __shfl_xor_sync(0xFFFFFFFF, b, 2);
                const float m = a * (1.0f / 64.0f);
                const float var = b * (1.0f / 64.0f) - m * m;
                const float r = rsqrtf(var + 1e-5f);
                rs[rr] = r;
                cc[rr] = -m * r;
            }

            if (l < 2) {
                #pragma unroll
                for (int kc = 0; kc < 4; kc++) {
                    const float n00 = fmaf(acc[2 * kc][0],     rs[0], cc[0]);
                    const float n01 = fmaf(acc[2 * kc][1],     rs[0], cc[0]);
                    const float n02 = fmaf(acc[2 * kc][2],     rs[1], cc[1]);
                    const float n03 = fmaf(acc[2 * kc][3],     rs[1], cc[1]);
                    const float n10 = fmaf(acc[2 * kc + 1][0], rs[0], cc[0]);
                    const float n11 = fmaf(acc[2 * kc + 1][1], rs[0], cc[0]);
                    const float n12 = fmaf(acc[2 * kc + 1][2], rs[1], cc[1]);
                    const float n13 = fmaf(acc[2 * kc + 1][3], rs[1], cc[1]);
                    splitpk(n00, n01, ahi[kc][0], alo[kc][0]);
                    splitpk(n02, n03, ahi[kc][1], alo[kc][1]);
                    splitpk(n10, n11, ahi[kc][2], alo[kc][2]);
                    splitpk(n12, n13, ahi[kc][3], alo[kc][3]);
                }
            }
        }

        // final 64 -> 5 projection with inline LN apply
        float o[2][VOCAB];
        #pragma unroll
        for (int rr = 0; rr < 2; rr++) {
            o[rr][0] = bo0; o[rr][1] = bo1; o[rr][2] = bo2;
            o[rr][3] = bo3; o[rr][4] = bo4;
        }
        #pragma unroll
        for (int nt = 0; nt < 8; nt++) {
            const int c0 = nt * 8 + tq * 2;
            const float4 wa = *(const float4*)(sWo8 + c0 * 8);
            const float  wa4 = sWo8[c0 * 8 + 4];
            const float4 wb = *(const float4*)(sWo8 + (c0 + 1) * 8);
            const float  wb4 = sWo8[(c0 + 1) * 8 + 4];
            #pragma unroll
            for (int rr = 0; rr < 2; rr++) {
                const float h0 = fmaf(acc[nt][2 * rr],     rs[rr], cc[rr]);
                const float h1 = fmaf(acc[nt][2 * rr + 1], rs[rr], cc[rr]);
                o[rr][0] = fmaf(h0, wa.x, fmaf(h1, wb.x, o[rr][0]));
                o[rr][1] = fmaf(h0, wa.y, fmaf(h1, wb.y, o[rr][1]));
                o[rr][2] = fmaf(h0, wa.z, fmaf(h1, wb.z, o[rr][2]));
                o[rr][3] = fmaf(h0, wa.w, fmaf(h1, wb.w, o[rr][3]));
                o[rr][4] = fmaf(h0, wa4,  fmaf(h1, wb4,  o[rr][4]));
            }
        }
        #pragma unroll
        for (int rr = 0; rr < 2; rr++) {
            #pragma unroll
            for (int v = 0; v < VOCAB; v++) {
                float t = o[rr][v];
                t += __shfl_xor_sync(0xFFFFFFFF, t, 1);
                t += __shfl_xor_sync(0xFFFFFFFF, t, 2);
                o[rr][v] = t;
            }
            const int row = rowbase + q + 8 * rr;
            float* op = out + (size_t)row * VOCAB;
            const float val = (tq & 2) ? ((tq & 1) ? o[rr][3] : o[rr][2])
                                       : ((tq & 1) ? o[rr][1] : o[rr][0]);
            op[tq] = val;
            if (tq == 0) op[4] = o[rr][4];
        }
    }
}

// ---- tiled symmetrization ----
#define NT (S / 32)
#define TROW 160
#define TPAD 165
__global__ void symmetrize_tiled(float* __restrict__ out) {
    __shared__ float sA[32 * TPAD];
    __shared__ float sBt[32 * TPAD];
    int tp = blockIdx.x;
    const int b = blockIdx.y;
    int ti = 0;
    while (tp >= NT - ti) { tp -= NT - ti; ti++; }
    const int tj = ti + tp;
    const int bi = ti * 32, bj = tj * 32;
    const int tid = threadIdx.x;

    for (int f = tid; f < 32 * TROW; f += 256) {
        int r = f / TROW, c = f % TROW;
        sA [r * TPAD + c] = out[((size_t)(b * S + bi + r) * S + bj) * VOCAB + c];
        sBt[r * TPAD + c] = out[((size_t)(b * S + bj + r) * S + bi) * VOCAB + c];
    }
    __syncthreads();
    for (int f = tid; f < 32 * TROW; f += 256) {
        int r = f / TROW, c = f % TROW;
        int jj = c / VOCAB, v = c % VOCAB;
        float m = 0.5f * (sA[r * TPAD + c] + sBt[jj * TPAD + r * VOCAB + v]);
        out[((size_t)(b * S + bi + r) * S + bj) * VOCAB + c] = m;
    }
    for (int f = tid; f < 32 * TROW; f += 256) {
        int r = f / TROW, c = f % TROW;
        int jj = c / VOCAB, v = c % VOCAB;
        float m = 0.5f * (sBt[r * TPAD + c] + sA[jj * TPAD + r * VOCAB + v]);
        out[((size_t)(b * S + bj + r) * S + bi) * VOCAB + c] = m;
    }
}

extern "C" void kernel_launch(void* const* d_in, const int* in_sizes, int n_in,
                              void* d_out, int out_size) {
    const float* x    = (const float*)d_in[0];
    const float* W1   = (const float*)d_in[1];
    const float* b1   = (const float*)d_in[2];
    const float* W2   = (const float*)d_in[3];
    const float* b2   = (const float*)d_in[4];
    const float* W3   = (const float*)d_in[5];
    const float* b3   = (const float*)d_in[6];
    const float* ln_g = (const float*)d_in[7];
    const float* ln_b = (const float*)d_in[8];
    const float* Wo   = (const float*)d_in[9];
    const float* bo   = (const float*)d_in[10];
    float* out = (float*)d_out;

    static bool attr_set = false;
    if (!attr_set) {
        cudaFuncSetAttribute(mma_mlp_kernel,
                             cudaFuncAttributeMaxDynamicSharedMemorySize, SMEM_BYTES);
        attr_set = true;
    }

    prep_weights<<<(3 * 2 * 4 * 8 * 32 + 255) / 256, 256>>>(W1, W2, W3, ln_g);
    prep_fold<<<1, 256>>>(W2, b2, W3, b3, ln_g, ln_b, Wo, bo);
    mma_mlp_kernel<<<GRID_MAIN, TPB, SMEM_BYTES>>>(x, b1, out);

    dim3 gsym(NT * (NT + 1) / 2, BATCH);
    symmetrize_tiled<<<gsym, 256>>>(out);
}

// round 10
// speedup vs baseline: 1.2589x; 1.2589x over previous
#include <cuda_runtime.h>
#include <cuda_bf16.h>
#include <math.h>
#include <stdint.h>

#define H 64
#define VOCAB 5
#define S 384
#define BATCH 8
#define NROWS (BATCH * S * S)     // 1,179,648
#define NTILES (NROWS / 128)      // 9216 tiles of 128 rows (32 per warp)
#define TPB 128
#define GRID_MAIN 296             // 148 SMs * 2 resident CTAs

// ---- dynamic smem layout (bytes) ----
#define SM_BF    0                   // uint2[3][2][4][8][32] = 49152
#define SM_WO8   49152               // float[64*8] = 2048
#define SM_BIAS  (SM_WO8 + 2048)     // float[3*64] = 768
#define SM_BOP   (SM_BIAS + 768)     // float[8]
#define SMEM_BYTES (SM_BOP + 32)     // 52000

static __device__ __forceinline__ unsigned short bfu(__nv_bfloat16 h) {
    return __bfloat16_as_ushort(h);
}

static __device__ __forceinline__ void splitpk(float a, float b, uint32_t& hp, uint32_t& lp) {
    __nv_bfloat162 h2 = __floats2bfloat162_rn(a, b);
    uint32_t u = *(uint32_t*)&h2;
    float ha = __uint_as_float(u << 16);
    float hb = __uint_as_float(u & 0xFFFF0000u);
    __nv_bfloat162 l2 = __floats2bfloat162_rn(a - ha, b - hb);
    hp = u;
    lp = *(uint32_t*)&l2;
}

// Branch-free exact-gelu, A&S 7.1.25 erf (3-term, abs err <= 2.5e-5)
static __device__ __forceinline__ float gelu_f(float v) {
    const float z  = fabsf(v) * 0.70710678118654752f;
    const float t  = __fdividef(1.0f, fmaf(0.47047f, z, 1.0f));
    float p = fmaf(0.7478556f, t, -0.0958798f);
    p = fmaf(p, t, 0.3480242f);
    p = p * t;
    const float e  = __expf(-z * z);
    const float er = fmaf(-p, e, 1.0f);
    const float es = copysignf(er, v);
    const float hv = 0.5f * v;
    return fmaf(hv, es, hv);
}

#define MMA(d, a, bx, by)                                                              \
    asm volatile("mma.sync.aligned.m16n8k16.row.col.f32.bf16.bf16.f32 "                \
        "{%0,%1,%2,%3}, {%4,%5,%6,%7}, {%8,%9}, {%0,%1,%2,%3};"                        \
        : "+f"(d[0]), "+f"(d[1]), "+f"(d[2]), "+f"(d[3])                               \
        : "r"(a[0]), "r"(a[1]), "r"(a[2]), "r"(a[3]), "r"(bx), "r"(by))

__global__ __launch_bounds__(TPB, 2)
void mma_mlp_kernel(const float* __restrict__ x,
                    const float* __restrict__ W1, const float* __restrict__ b1,
                    const float* __restrict__ W2, const float* __restrict__ b2,
                    const float* __restrict__ W3, const float* __restrict__ b3,
                    const float* __restrict__ ln_g, const float* __restrict__ ln_b,
                    const float* __restrict__ Wo, const float* __restrict__ bo,
                    float* __restrict__ out) {
    extern __shared__ __align__(16) unsigned char smem[];
    uint2*  sBF   = (uint2*)(smem + SM_BF);     // [3][2][4][8][32]
    float*  sWo8  = (float*)(smem + SM_WO8);
    float*  sBias = (float*)(smem + SM_BIAS);
    float*  sBop  = (float*)(smem + SM_BOP);

    const int tid  = threadIdx.x;
    const int lane = tid & 31;
    const int warp = tid >> 5;
    const int q    = lane >> 2;
    const int tq   = lane & 3;

    // ---- in-kernel prep: B fragments (gamma-folded for layers 1,2) ----
    for (int idx = tid; idx < 3 * 2 * 4 * 8 * 32; idx += TPB) {
        int fl = idx & 31;
        int nt = (idx >> 5) & 7;
        int ks = (idx >> 8) & 3;
        int t  = (idx >> 10) & 1;
        int l  = idx >> 11;
        const float* W = (l == 0) ? W1 : (l == 1) ? W2 : W3;
        int n  = nt * 8 + (fl >> 2);
        int k0 = ks * 16 + (fl & 3) * 2;
        int kk[4] = {k0, k0 + 1, k0 + 8, k0 + 9};
        unsigned short e[4];
        #pragma unroll
        for (int i = 0; i < 4; i++) {
            float w = W[kk[i] * H + n];
            if (l > 0) w *= ln_g[kk[i]];
            __nv_bfloat16 hi = __float2bfloat16_rn(w);
            e[i] = t ? bfu(__float2bfloat16_rn(w - __bfloat162float(hi))) : bfu(hi);
        }
        uint2 r;
        r.x = (uint32_t)e[0] | ((uint32_t)e[1] << 16);
        r.y = (uint32_t)e[2] | ((uint32_t)e[3] << 16);
        sBF[idx] = r;
    }
    // ---- folded biases, gamma-scaled Wo, beta-folded bo ----
    if (tid < 64) {
        float s2 = b2[tid], s3 = b3[tid];
        for (int k = 0; k < 64; k++) {
            const float lb = ln_b[k];
            s2 = fmaf(lb, W2[k * H + tid], s2);
            s3 = fmaf(lb, W3[k * H + tid], s3);
        }
        sBias[tid] = b1[tid];
        sBias[64 + tid] = s2;
        sBias[128 + tid] = s3;
    } else if (tid < 128) {
        int k = tid - 64;
        const float g = ln_g[k];
        #pragma unroll
        for (int v = 0; v < 8; v++)
            sWo8[k * 8 + v] = (v < VOCAB) ? g * Wo[k * VOCAB + v] : 0.0f;
        if (k < VOCAB) {
            float s = bo[k];
            for (int kk2 = 0; kk2 < 64; kk2++) s = fmaf(ln_b[kk2], Wo[kk2 * VOCAB + k], s);
            sBop[k] = s;
        }
    }
    __syncthreads();

    const float bo0 = sBop[0], bo1 = sBop[1], bo2 = sBop[2],
                bo3 = sBop[3], bo4 = sBop[4];

    for (int tile = blockIdx.x; tile < NTILES; tile += gridDim.x) {
        const int rowbase = tile * 128 + warp * 32;
        const float* xb = x + (size_t)rowbase * H;

        // load x into A fragments (hi/lo bf16 split), 32 rows per warp
        uint32_t ahi[2][4][4], alo[2][4][4];
        #pragma unroll
        for (int mt = 0; mt < 2; mt++)
            #pragma unroll
            for (int kc = 0; kc < 4; kc++)
                #pragma unroll
                for (int h2 = 0; h2 < 2; h2++)
                    #pragma unroll
                    for (int rr = 0; rr < 2; rr++) {
                        const float2 v = *(const float2*)(xb + (size_t)(mt * 16 + q + 8 * rr) * H
                                                          + kc * 16 + h2 * 8 + tq * 2);
                        splitpk(v.x, v.y, ahi[mt][kc][h2 * 2 + rr], alo[mt][kc][h2 * 2 + rr]);
                    }

        float acc[2][8][4];
        float rs[2][2], cc[2][2];
        #pragma unroll
        for (int l = 0; l < 3; l++) {
            #pragma unroll
            for (int nt = 0; nt < 8; nt++) {
                const float2 bb = *(const float2*)(sBias + l * 64 + nt * 8 + tq * 2);
                #pragma unroll
                for (int mt = 0; mt < 2; mt++) {
                    acc[mt][nt][0] = bb.x; acc[mt][nt][1] = bb.y;
                    acc[mt][nt][2] = bb.x; acc[mt][nt][3] = bb.y;
                }
            }
            #pragma unroll
            for (int ks = 0; ks < 4; ks++) {
                #pragma unroll
                for (int nt = 0; nt < 8; nt++) {
                    const uint2 bh = sBF[(((l * 2 + 0) * 4 + ks) * 8 + nt) * 32 + lane];
                    const uint2 bl = sBF[(((l * 2 + 1) * 4 + ks) * 8 + nt) * 32 + lane];
                    MMA(acc[0][nt], ahi[0][ks], bh.x, bh.y);
                    MMA(acc[1][nt], ahi[1][ks], bh.x, bh.y);
                    MMA(acc[0][nt], alo[0][ks], bh.x, bh.y);
                    MMA(acc[1][nt], alo[1][ks], bh.x, bh.y);
                    MMA(acc[0][nt], ahi[0][ks], bl.x, bl.y);
                    MMA(acc[1][nt], ahi[1][ks], bl.x, bl.y);
                }
            }

            // gelu + LN statistics
            float s0[2][2] = {{0, 0}, {0, 0}}, s1[2][2] = {{0, 0}, {0, 0}};
            #pragma unroll
            for (int mt = 0; mt < 2; mt++)
                #pragma unroll
                for (int nt = 0; nt < 8; nt++)
                    #pragma unroll
                    for (int i = 0; i < 4; i++) {
                        const float g = gelu_f(acc[mt][nt][i]);
                        acc[mt][nt][i] = g;
                        s0[mt][i >> 1] += g;
                        s1[mt][i >> 1] += g * g;
                    }
            #pragma unroll
            for (int mt = 0; mt < 2; mt++)
                #pragma unroll
                for (int rr = 0; rr < 2; rr++) {
                    float a = s0[mt][rr], b = s1[mt][rr];
                    a += __shfl_xor_sync(0xFFFFFFFF, a, 1);
                    b += __shfl_xor_sync(0xFFFFFFFF, b, 1);
                    a += __shfl_xor_sync(0xFFFFFFFF, a, 2);
                    b += __shfl_xor_sync(0xFFFFFFFF, b, 2);
                    const float m = a * (1.0f / 64.0f);
                    const float var = b * (1.0f / 64.0f) - m * m;
                    const float r = rsqrtf(var + 1e-5f);
                    rs[mt][rr] = r;
                    cc[mt][rr] = -m * r;
                }

            if (l < 2) {
                #pragma unroll
                for (int mt = 0; mt < 2; mt++)
                    #pragma unroll
                    for (int kc = 0; kc < 4; kc++) {
                        const float n00 = fmaf(acc[mt][2 * kc][0],     rs[mt][0], cc[mt][0]);
                        const float n01 = fmaf(acc[mt][2 * kc][1],     rs[mt][0], cc[mt][0]);
                        const float n02 = fmaf(acc[mt][2 * kc][2],     rs[mt][1], cc[mt][1]);
                        const float n03 = fmaf(acc[mt][2 * kc][3],     rs[mt][1], cc[mt][1]);
                        const float n10 = fmaf(acc[mt][2 * kc + 1][0], rs[mt][0], cc[mt][0]);
                        const float n11 = fmaf(acc[mt][2 * kc + 1][1], rs[mt][0], cc[mt][0]);
                        const float n12 = fmaf(acc[mt][2 * kc + 1][2], rs[mt][1], cc[mt][1]);
                        const float n13 = fmaf(acc[mt][2 * kc + 1][3], rs[mt][1], cc[mt][1]);
                        splitpk(n00, n01, ahi[mt][kc][0], alo[mt][kc][0]);
                        splitpk(n02, n03, ahi[mt][kc][1], alo[mt][kc][1]);
                        splitpk(n10, n11, ahi[mt][kc][2], alo[mt][kc][2]);
                        splitpk(n12, n13, ahi[mt][kc][3], alo[mt][kc][3]);
                    }
            }
        }

        // L2 prefetch of next tile's x rows (zero register cost)
        {
            const int ntile = tile + gridDim.x;
            if (ntile < NTILES) {
                const char* nx = (const char*)(x + ((size_t)ntile * 128 + warp * 32 + q) * H) + tq * 64;
                asm volatile("prefetch.global.L2 [%0];" :: "l"(nx));
                asm volatile("prefetch.global.L2 [%0];" :: "l"(nx + 8 * H * 4));
                asm volatile("prefetch.global.L2 [%0];" :: "l"(nx + 16 * H * 4));
                asm volatile("prefetch.global.L2 [%0];" :: "l"(nx + 24 * H * 4));
            }
        }

        // final 64 -> 5 projection with inline LN apply
        float o[2][2][VOCAB];
        #pragma unroll
        for (int mt = 0; mt < 2; mt++)
            #pragma unroll
            for (int rr = 0; rr < 2; rr++) {
                o[mt][rr][0] = bo0; o[mt][rr][1] = bo1; o[mt][rr][2] = bo2;
                o[mt][rr][3] = bo3; o[mt][rr][4] = bo4;
            }
        #pragma unroll
        for (int nt = 0; nt < 8; nt++) {
            const int c0 = nt * 8 + tq * 2;
            const float4 wa = *(const float4*)(sWo8 + c0 * 8);
            const float  wa4 = sWo8[c0 * 8 + 4];
            const float4 wb = *(const float4*)(sWo8 + (c0 + 1) * 8);
            const float  wb4 = sWo8[(c0 + 1) * 8 + 4];
            #pragma unroll
            for (int mt = 0; mt < 2; mt++)
                #pragma unroll
                for (int rr = 0; rr < 2; rr++) {
                    const float h0 = fmaf(acc[mt][nt][2 * rr],     rs[mt][rr], cc[mt][rr]);
                    const float h1 = fmaf(acc[mt][nt][2 * rr + 1], rs[mt][rr], cc[mt][rr]);
                    o[mt][rr][0] = fmaf(h0, wa.x, fmaf(h1, wb.x, o[mt][rr][0]));
                    o[mt][rr][1] = fmaf(h0, wa.y, fmaf(h1, wb.y, o[mt][rr][1]));
                    o[mt][rr][2] = fmaf(h0, wa.z, fmaf(h1, wb.z, o[mt][rr][2]));
                    o[mt][rr][3] = fmaf(h0, wa.w, fmaf(h1, wb.w, o[mt][rr][3]));
                    o[mt][rr][4] = fmaf(h0, wa4,  fmaf(h1, wb4,  o[mt][rr][4]));
                }
        }
        #pragma unroll
        for (int mt = 0; mt < 2; mt++)
            #pragma unroll
            for (int rr = 0; rr < 2; rr++) {
                #pragma unroll
                for (int v = 0; v < VOCAB; v++) {
                    float t = o[mt][rr][v];
                    t += __shfl_xor_sync(0xFFFFFFFF, t, 1);
                    t += __shfl_xor_sync(0xFFFFFFFF, t, 2);
                    o[mt][rr][v] = t;
                }
                const int row = rowbase + mt * 16 + q + 8 * rr;
                float* op = out + (size_t)row * VOCAB;
                const float val = (tq & 2) ? ((tq & 1) ? o[mt][rr][3] : o[mt][rr][2])
                                           : ((tq & 1) ? o[mt][rr][1] : o[mt][rr][0]);
                op[tq] = val;
                if (tq == 0) op[4] = o[mt][rr][4];
            }
    }
}

// ---- tiled symmetrization: 16x16 row-pair tiles, 128-thread blocks ----
#define NT2 24
#define TROW2 80     // 16 cols * 5 vocab
#define TPAD2 85
__global__ void symmetrize_tiled(float* __restrict__ out) {
    __shared__ float sA[16 * TPAD2];
    __shared__ float sBt[16 * TPAD2];
    int tp = blockIdx.x;
    const int b = blockIdx.y;
    int ti = 0;
    while (tp >= NT2 - ti) { tp -= NT2 - ti; ti++; }
    const int tj = ti + tp;
    const int bi = ti * 16, bj = tj * 16;
    const int tid = threadIdx.x;

    for (int f = tid; f < 16 * TROW2; f += 128) {
        int r = f / TROW2, c = f % TROW2;
        sA [r * TPAD2 + c] = out[((size_t)(b * S + bi + r) * S + bj) * VOCAB + c];
        sBt[r * TPAD2 + c] = out[((size_t)(b * S + bj + r) * S + bi) * VOCAB + c];
    }
    __syncthreads();
    for (int f = tid; f < 16 * TROW2; f += 128) {
        int r = f / TROW2, c = f % TROW2;
        int jj = c / VOCAB, v = c % VOCAB;
        float m = 0.5f * (sA[r * TPAD2 + c] + sBt[jj * TPAD2 + r * VOCAB + v]);
        out[((size_t)(b * S + bi + r) * S + bj) * VOCAB + c] = m;
    }
    for (int f = tid; f < 16 * TROW2; f += 128) {
        int r = f / TROW2, c = f % TROW2;
        int jj = c / VOCAB, v = c % VOCAB;
        float m = 0.5f * (sBt[r * TPAD2 + c] + sA[jj * TPAD2 + r * VOCAB + v]);
        out[((size_t)(b * S + bj + r) * S + bi) * VOCAB + c] = m;
    }
}

extern "C" void kernel_launch(void* const* d_in, const int* in_sizes, int n_in,
                              void* d_out, int out_size) {
    const float* x    = (const float*)d_in[0];
    const float* W1   = (const float*)d_in[1];
    const float* b1   = (const float*)d_in[2];
    const float* W2   = (const float*)d_in[3];
    const float* b2   = (const float*)d_in[4];
    const float* W3   = (const float*)d_in[5];
    const float* b3   = (const float*)d_in[6];
    const float* ln_g = (const float*)d_in[7];
    const float* ln_b = (const float*)d_in[8];
    const float* Wo   = (const float*)d_in[9];
    const float* bo   = (const float*)d_in[10];
    float* out = (float*)d_out;

    static bool attr_set = false;
    if (!attr_set) {
        cudaFuncSetAttribute(mma_mlp_kernel,
                             cudaFuncAttributeMaxDynamicSharedMemorySize, SMEM_BYTES);
        attr_set = true;
    }

    mma_mlp_kernel<<<GRID_MAIN, TPB, SMEM_BYTES>>>(x, W1, b1, W2, b2, W3, b3,
                                                   ln_g, ln_b, Wo, bo, out);

    dim3 gsym(NT2 * (NT2 + 1) / 2, BATCH);
    symmetrize_tiled<<<gsym, 128>>>(out);
}